// round 6
// baseline (speedup 1.0000x reference)
#include <cuda_runtime.h>
#include <cstdint>

#define B_   4
#define N_   16384
#define C_   64
#define S_   2048
#define K_   32
#define M_   (B_*S_*K_)
#define CO_  128
#define KP0_ 72

__device__ __align__(16) float g_newxyz[B_*S_*3];
__device__ int   g_idx[B_*S_*K_];
__device__ __align__(16) float g_ptsT[(size_t)B_*N_*C_];
__device__ float g_pnorm[B_*N_];
__device__ __align__(16) float g_X0[(size_t)M_*KP0_];
__device__ __align__(16) float g_Ybuf[(size_t)M_*CO_];
__device__ __align__(16) float g_Xbuf[(size_t)M_*CO_];
__device__ __align__(16) float g_Hbuf[(size_t)M_*CO_];
__device__ __align__(16) float g_Wp[CO_*KP0_];
__device__ float g_sum[CO_], g_sq[CO_], g_scale[CO_], g_shift[CO_];

__global__ void transpose_pts(const float* __restrict__ pts){
    __shared__ float tile[32][33];
    int b=blockIdx.z, n0=blockIdx.x<<5, c0=blockIdx.y<<5;
    int tx=threadIdx.x, ty=threadIdx.y;
    tile[ty][tx]=pts[((size_t)b*C_+(c0+ty))*N_+n0+tx];
    __syncthreads();
    g_ptsT[((size_t)b*N_+(n0+ty))*C_+c0+tx]=tile[tx][ty];
}

__global__ void pnorm_kernel(const float* __restrict__ xyz){
    int id=blockIdx.x*blockDim.x+threadIdx.x;
    if(id>=B_*N_) return;
    int b=id/N_, n=id%N_;
    const float* Xp=xyz+(size_t)b*3*N_;
    float x=Xp[n], y=Xp[N_+n], z=Xp[2*N_+n];
    // greedy LLVM contraction form: fma(z,z, fma(x,x, y*y))
    g_pnorm[id]=fmaf(z,z,fmaf(x,x,y*y));
}

__global__ void wpad_kernel(const float* __restrict__ w){
    int id=blockIdx.x*blockDim.x+threadIdx.x;
    if(id>=CO_*KP0_) return;
    int o=id/KP0_, k=id%KP0_;
    g_Wp[id]=(k<67)?w[o*67+k]:0.0f;
}

__global__ void __launch_bounds__(1024,1) fps_kernel(const float* __restrict__ xyz,
                                                     float* __restrict__ out0){
    extern __shared__ float fsm[];
    const int b=blockIdx.x, t=threadIdx.x;
    const float* Xp=xyz+(size_t)b*3*N_;
    float* sx=fsm; float* sy=fsm+N_; float* sz=fsm+2*N_;
    __shared__ float redv[32]; __shared__ int redi[32];
    __shared__ int s_win; __shared__ float s_c[3];
    float px[8],py[8],pz[8],dmin[16];
#pragma unroll
    for(int i=0;i<8;i++){
        int n=i*1024+t;
        float x=Xp[n],y=Xp[N_+n],z=Xp[2*N_+n];
        sx[n]=x; sy[n]=y; sz[n]=z; px[i]=x; py[i]=y; pz[i]=z; dmin[i]=1e10f;
    }
#pragma unroll
    for(int i=8;i<16;i++){
        int n=i*1024+t;
        sx[n]=Xp[n]; sy[n]=Xp[N_+n]; sz[n]=Xp[2*N_+n]; dmin[i]=1e10f;
    }
    int cur=0;
    const int warp=t>>5, lane=t&31;
    for(int it=0; it<S_; ++it){
        if(t==0){
            float cx=sx[cur],cy=sy[cur],cz=sz[cur];
            s_c[0]=cx; s_c[1]=cy; s_c[2]=cz;
            out0[(size_t)b*3*S_+it]=cx;
            out0[(size_t)b*3*S_+S_+it]=cy;
            out0[(size_t)b*3*S_+2*S_+it]=cz;
            float* nz=g_newxyz+((size_t)b*S_+it)*3;
            nz[0]=cx; nz[1]=cy; nz[2]=cz;
        }
        __syncthreads();
        const float cx=s_c[0],cy=s_c[1],cz=s_c[2];
        float bv=-1.0f; int bi=0;
#pragma unroll
        for(int i=0;i<8;i++){
            float dx=px[i]-cx, dy=py[i]-cy, dz=pz[i]-cz;
            // greedy contraction: fma(dz,dz, fma(dx,dx, dy*dy))
            float d=fmaf(dz,dz,fmaf(dx,dx,dy*dy));
            float dm=fminf(dmin[i],d); dmin[i]=dm;
            if(dm>bv){bv=dm; bi=i*1024+t;}
        }
#pragma unroll
        for(int i=8;i<16;i++){
            int n=i*1024+t;
            float dx=sx[n]-cx, dy=sy[n]-cy, dz=sz[n]-cz;
            float d=fmaf(dz,dz,fmaf(dx,dx,dy*dy));
            float dm=fminf(dmin[i],d); dmin[i]=dm;
            if(dm>bv){bv=dm; bi=n;}
        }
#pragma unroll
        for(int off=16; off>0; off>>=1){
            float ov=__shfl_down_sync(0xffffffffu,bv,off);
            int   oi=__shfl_down_sync(0xffffffffu,bi,off);
            if(ov>bv||(ov==bv&&oi<bi)){bv=ov; bi=oi;}
        }
        if(lane==0){redv[warp]=bv; redi[warp]=bi;}
        __syncthreads();
        if(warp==0){
            bv=redv[lane]; bi=redi[lane];
#pragma unroll
            for(int off=16; off>0; off>>=1){
                float ov=__shfl_down_sync(0xffffffffu,bv,off);
                int   oi=__shfl_down_sync(0xffffffffu,bi,off);
                if(ov>bv||(ov==bv&&oi<bi)){bv=ov; bi=oi;}
            }
            if(lane==0) s_win=bi;
        }
        __syncthreads();
        cur=s_win;
    }
}

__global__ void query_kernel(const float* __restrict__ xyz){
    int gw=(blockIdx.x*blockDim.x+threadIdx.x)>>5;
    int lane=threadIdx.x&31;
    if(gw>=B_*S_) return;
    int b=gw/S_;
    const float* nz=g_newxyz+(size_t)gw*3;
    float cx=nz[0],cy=nz[1],cz=nz[2];
    float srcn=fmaf(cz,cz,fmaf(cx,cx,cy*cy));
    const float* Xp=xyz+(size_t)b*3*N_;
    const float* pn=g_pnorm+(size_t)b*N_;
    int* dst=g_idx+(size_t)gw*K_;
    int count=0, first=0; bool haveFirst=false;
    for(int base=0; base<N_; base+=32){
        int n=base+lane;
        float dot=fmaf(cz,Xp[2*N_+n],fmaf(cy,Xp[N_+n],cx*Xp[n]));
        float d=fmaf(-2.0f,dot,srcn)+pn[n];
        bool ok=!(d>0.04f);
        unsigned m=__ballot_sync(0xffffffffu,ok);
        if(m){
            if(!haveFirst){first=base+__ffs(m)-1; haveFirst=true;}
            int rank=__popc(m&((1u<<lane)-1u));
            if(ok&&(count+rank)<K_) dst[count+rank]=n;
            count+=__popc(m);
            if(count>=K_) break;
        }
    }
    if(count<K_){
        for(int sl=count+lane; sl<K_; sl+=32) dst[sl]=first;
    }
}

__global__ void buildx_kernel(const float* __restrict__ xyz){
    int row=(blockIdx.x*blockDim.x+threadIdx.x)>>5;
    int lane=threadIdx.x&31;
    if(row>=M_) return;
    int b=row>>16;
    int cent=row>>5;
    int j=g_idx[row];
    const float* nz=g_newxyz+(size_t)cent*3;
    float* dst=g_X0+(size_t)row*KP0_;
    const float* src=g_ptsT+((size_t)b*N_+j)*C_;
#pragma unroll
    for(int c0=0;c0<KP0_;c0+=32){
        int c=c0+lane;
        if(c<KP0_){
            float v;
            if(c<3)       v=xyz[(size_t)b*3*N_+(size_t)c*N_+j]-nz[c];
            else if(c<67) v=src[c-3];
            else          v=0.0f;
            dst[c]=v;
        }
    }
}

template<int K>
__global__ void __launch_bounds__(256,2) sgemm_kernel(const float* __restrict__ A,
                                                      const float* __restrict__ W,
                                                      float* __restrict__ Y){
    __shared__ float As[8][128];
    __shared__ float Bs[8][128];
    const int tid=threadIdx.x, m0=blockIdx.x<<7;
    const int tm=tid>>4, tn=tid&15;
    const int lrow=tid>>1, lcol=(tid&1)<<2;
    const float* Aptr=A+(size_t)(m0+lrow)*K+lcol;
    const float* Wptr=W+(size_t)lrow*K+lcol;
    float acc[8][8];
#pragma unroll
    for(int i=0;i<8;i++)
#pragma unroll
        for(int j=0;j<8;j++) acc[i][j]=0.0f;
    for(int k0=0;k0<K;k0+=8){
        float4 av=*reinterpret_cast<const float4*>(Aptr+k0);
        float4 wv=*reinterpret_cast<const float4*>(Wptr+k0);
        As[lcol+0][lrow]=av.x; As[lcol+1][lrow]=av.y; As[lcol+2][lrow]=av.z; As[lcol+3][lrow]=av.w;
        Bs[lcol+0][lrow]=wv.x; Bs[lcol+1][lrow]=wv.y; Bs[lcol+2][lrow]=wv.z; Bs[lcol+3][lrow]=wv.w;
        __syncthreads();
#pragma unroll
        for(int kk=0;kk<8;kk++){
            float4 a0=*reinterpret_cast<const float4*>(&As[kk][tm<<3]);
            float4 a1=*reinterpret_cast<const float4*>(&As[kk][(tm<<3)+4]);
            float4 b0=*reinterpret_cast<const float4*>(&Bs[kk][tn<<3]);
            float4 b1=*reinterpret_cast<const float4*>(&Bs[kk][(tn<<3)+4]);
            float a[8]={a0.x,a0.y,a0.z,a0.w,a1.x,a1.y,a1.z,a1.w};
            float w8[8]={b0.x,b0.y,b0.z,b0.w,b1.x,b1.y,b1.z,b1.w};
#pragma unroll
            for(int i=0;i<8;i++)
#pragma unroll
                for(int j=0;j<8;j++) acc[i][j]=fmaf(a[i],w8[j],acc[i][j]);
        }
        __syncthreads();
    }
#pragma unroll
    for(int i=0;i<8;i++){
        float* yp=Y+(size_t)(m0+(tm<<3)+i)*CO_+(tn<<3);
        *reinterpret_cast<float4*>(yp)  =make_float4(acc[i][0],acc[i][1],acc[i][2],acc[i][3]);
        *reinterpret_cast<float4*>(yp+4)=make_float4(acc[i][4],acc[i][5],acc[i][6],acc[i][7]);
    }
}

__global__ void stats_zero(){
    int c=threadIdx.x;
    if(c<CO_){g_sum[c]=0.f; g_sq[c]=0.f;}
}

__global__ void stats_kernel(const float* __restrict__ Y){
    int c=threadIdx.x&127, half=threadIdx.x>>7;
    size_t row0=(size_t)blockIdx.x*512+(size_t)half*256;
    const float* p=Y+row0*CO_+c;
    float s=0.f,q=0.f;
#pragma unroll 4
    for(int r=0;r<256;r++){float v=p[(size_t)r*CO_]; s+=v; q=fmaf(v,v,q);}
    __shared__ float sh[256];
    sh[threadIdx.x]=s; __syncthreads();
    if(half==0) atomicAdd(&g_sum[c], sh[c]+sh[c+128]);
    __syncthreads();
    sh[threadIdx.x]=q; __syncthreads();
    if(half==0) atomicAdd(&g_sq[c], sh[c]+sh[c+128]);
}

__global__ void finalize_kernel(const float* __restrict__ gg, const float* __restrict__ bb){
    int c=threadIdx.x;
    if(c<CO_){
        const float inv=1.0f/(float)M_;
        float mu=g_sum[c]*inv;
        float var=g_sq[c]*inv-mu*mu;
        float rs=rsqrtf(var+1e-5f);
        float sc=gg[c]*rs;
        g_scale[c]=sc;
        g_shift[c]=bb[c]-mu*sc;
    }
}

__global__ void bnrelu_kernel(const float4* __restrict__ Y, float4* __restrict__ X){
    size_t i=(size_t)blockIdx.x*blockDim.x+threadIdx.x;
    int c4=(int)(i&31)<<2;
    float4 y=Y[i],o;
    o.x=fmaxf(0.f,fmaf(y.x,g_scale[c4+0],g_shift[c4+0]));
    o.y=fmaxf(0.f,fmaf(y.y,g_scale[c4+1],g_shift[c4+1]));
    o.z=fmaxf(0.f,fmaf(y.z,g_scale[c4+2],g_shift[c4+2]));
    o.w=fmaxf(0.f,fmaf(y.w,g_scale[c4+3],g_shift[c4+3]));
    X[i]=o;
}

__global__ void bnresrelu_kernel(const float4* __restrict__ Y, float4* __restrict__ X){
    size_t i=(size_t)blockIdx.x*blockDim.x+threadIdx.x;
    int c4=(int)(i&31)<<2;
    float4 y=Y[i], x=X[i], o;
    o.x=fmaxf(0.f,fmaf(y.x,g_scale[c4+0],g_shift[c4+0])+x.x);
    o.y=fmaxf(0.f,fmaf(y.y,g_scale[c4+1],g_shift[c4+1])+x.y);
    o.z=fmaxf(0.f,fmaf(y.z,g_scale[c4+2],g_shift[c4+2])+x.z);
    o.w=fmaxf(0.f,fmaf(y.w,g_scale[c4+3],g_shift[c4+3])+x.w);
    X[i]=o;
}

__global__ void maxpool_kernel(float* __restrict__ out2){
    int id=blockIdx.x*blockDim.x+threadIdx.x;
    int c=id&127;
    int s=(id>>7)&(S_-1);
    int b=id>>18;
    const float* p=g_Xbuf+((size_t)((b*S_)+s)*K_)*CO_+c;
    float m=p[0];
#pragma unroll
    for(int k=1;k<K_;k++) m=fmaxf(m,p[(size_t)k*CO_]);
    out2[((size_t)b*CO_+c)*S_+s]=m;
}

extern "C" void kernel_launch(void* const* d_in, const int* in_sizes, int n_in,
                              void* d_out, int out_size){
    const float* xyz  =(const float*)d_in[0];
    const float* pts  =(const float*)d_in[1];
    const float* wproj=(const float*)d_in[2];
    const float* gproj=(const float*)d_in[3];
    const float* bproj=(const float*)d_in[4];
    const float* w1   =(const float*)d_in[5];
    const float* w2   =(const float*)d_in[6];
    const float* g1   =(const float*)d_in[7];
    const float* b1   =(const float*)d_in[8];
    const float* g2   =(const float*)d_in[9];
    const float* b2   =(const float*)d_in[10];
    float* out=(float*)d_out;

    void *pX0v,*pYv,*pXv,*pHv,*pWpv;
    cudaGetSymbolAddress(&pX0v,g_X0);
    cudaGetSymbolAddress(&pYv, g_Ybuf);
    cudaGetSymbolAddress(&pXv, g_Xbuf);
    cudaGetSymbolAddress(&pHv, g_Hbuf);
    cudaGetSymbolAddress(&pWpv,g_Wp);
    float* pX0=(float*)pX0v; float* pY=(float*)pYv; float* pX=(float*)pXv;
    float* pH=(float*)pHv;   float* pWp=(float*)pWpv;

    cudaFuncSetAttribute(fps_kernel, cudaFuncAttributeMaxDynamicSharedMemorySize, 3*N_*4);

    transpose_pts<<<dim3(N_/32, C_/32, B_), dim3(32,32)>>>(pts);
    pnorm_kernel<<<(B_*N_+1023)/1024,1024>>>(xyz);
    wpad_kernel<<<(CO_*KP0_+1023)/1024,1024>>>(wproj);

    fps_kernel<<<B_,1024,3*N_*4>>>(xyz,out);
    query_kernel<<<(B_*S_*32)/256,256>>>(xyz);
    buildx_kernel<<<M_/8,256>>>(xyz);

    const int EW_GRID=(M_*CO_/4)/1024;

    sgemm_kernel<KP0_><<<M_/128,256>>>(pX0,pWp,pY);
    stats_zero<<<1,128>>>();
    stats_kernel<<<M_/512,256>>>(pY);
    finalize_kernel<<<1,128>>>(gproj,bproj);
    bnrelu_kernel<<<EW_GRID,1024>>>((const float4*)pY,(float4*)pX);

    for(int d=0; d<2; ++d){
        sgemm_kernel<128><<<M_/128,256>>>(pX, w1+(size_t)d*CO_*CO_, pY);
        stats_zero<<<1,128>>>();
        stats_kernel<<<M_/512,256>>>(pY);
        finalize_kernel<<<1,128>>>(g1+d*CO_, b1+d*CO_);
        bnrelu_kernel<<<EW_GRID,1024>>>((const float4*)pY,(float4*)pH);

        sgemm_kernel<128><<<M_/128,256>>>(pH, w2+(size_t)d*CO_*CO_, pY);
        stats_zero<<<1,128>>>();
        stats_kernel<<<M_/512,256>>>(pY);
        finalize_kernel<<<1,128>>>(g2+d*CO_, b2+d*CO_);
        bnresrelu_kernel<<<EW_GRID,1024>>>((const float4*)pY,(float4*)pX);
    }

    maxpool_kernel<<<(B_*S_*CO_)/256,256>>>(out + B_*3*S_);
}

// round 7
// speedup vs baseline: 1.0816x; 1.0816x over previous
#include <cuda_runtime.h>
#include <cstdint>

#define B_   4
#define N_   16384
#define C_   64
#define S_   2048
#define K_   32
#define M_   (B_*S_*K_)
#define CO_  128
#define KP0_ 72

__device__ __align__(16) float g_newxyz[B_*S_*3];
__device__ int   g_idx[B_*S_*K_];
__device__ __align__(16) float g_ptsT[(size_t)B_*N_*C_];
__device__ float g_pnorm[B_*N_];
__device__ __align__(16) float g_Ybuf[(size_t)M_*CO_];
__device__ __align__(16) float g_Xbuf[(size_t)M_*CO_];
__device__ __align__(16) float g_Hbuf[(size_t)M_*CO_];
__device__ __align__(16) float g_Wp[CO_*KP0_];
__device__ __align__(16) float g_sum[CO_];
__device__ __align__(16) float g_sq[CO_];
__device__ __align__(16) float g_scale[CO_];
__device__ __align__(16) float g_shift[CO_];

__global__ void transpose_pts(const float* __restrict__ pts){
    __shared__ float tile[32][33];
    int b=blockIdx.z, n0=blockIdx.x<<5, c0=blockIdx.y<<5;
    int tx=threadIdx.x, ty=threadIdx.y;
    tile[ty][tx]=pts[((size_t)b*C_+(c0+ty))*N_+n0+tx];
    __syncthreads();
    g_ptsT[((size_t)b*N_+(n0+ty))*C_+c0+tx]=tile[tx][ty];
}

__global__ void pnorm_kernel(const float* __restrict__ xyz){
    int id=blockIdx.x*blockDim.x+threadIdx.x;
    if(id>=B_*N_) return;
    int b=id/N_, n=id%N_;
    const float* Xp=xyz+(size_t)b*3*N_;
    float x=Xp[n], y=Xp[N_+n], z=Xp[2*N_+n];
    g_pnorm[id]=fmaf(z,z,fmaf(x,x,y*y));
}

__global__ void wpad_kernel(const float* __restrict__ w){
    int id=blockIdx.x*blockDim.x+threadIdx.x;
    if(id>=CO_*KP0_) return;
    int o=id/KP0_, k=id%KP0_;
    g_Wp[id]=(k<67)?w[o*67+k]:0.0f;
}

__global__ void __launch_bounds__(1024,1) fps_kernel(const float* __restrict__ xyz,
                                                     float* __restrict__ out0){
    extern __shared__ float fsm[];
    const int b=blockIdx.x, t=threadIdx.x;
    const float* Xp=xyz+(size_t)b*3*N_;
    float* sx=fsm; float* sy=fsm+N_; float* sz=fsm+2*N_;
    __shared__ float redv[32]; __shared__ int redi[32];
    __shared__ int s_win; __shared__ float s_c[3];
    float px[8],py[8],pz[8],dmin[16];
#pragma unroll
    for(int i=0;i<8;i++){
        int n=i*1024+t;
        float x=Xp[n],y=Xp[N_+n],z=Xp[2*N_+n];
        sx[n]=x; sy[n]=y; sz[n]=z; px[i]=x; py[i]=y; pz[i]=z; dmin[i]=1e10f;
    }
#pragma unroll
    for(int i=8;i<16;i++){
        int n=i*1024+t;
        sx[n]=Xp[n]; sy[n]=Xp[N_+n]; sz[n]=Xp[2*N_+n]; dmin[i]=1e10f;
    }
    int cur=0;
    const int warp=t>>5, lane=t&31;
    for(int it=0; it<S_; ++it){
        if(t==0){
            float cx=sx[cur],cy=sy[cur],cz=sz[cur];
            s_c[0]=cx; s_c[1]=cy; s_c[2]=cz;
            out0[(size_t)b*3*S_+it]=cx;
            out0[(size_t)b*3*S_+S_+it]=cy;
            out0[(size_t)b*3*S_+2*S_+it]=cz;
            float* nz=g_newxyz+((size_t)b*S_+it)*3;
            nz[0]=cx; nz[1]=cy; nz[2]=cz;
        }
        __syncthreads();
        const float cx=s_c[0],cy=s_c[1],cz=s_c[2];
        float bv=-1.0f; int bi=0;
#pragma unroll
        for(int i=0;i<8;i++){
            float dx=px[i]-cx, dy=py[i]-cy, dz=pz[i]-cz;
            float d=fmaf(dz,dz,fmaf(dx,dx,dy*dy));
            float dm=fminf(dmin[i],d); dmin[i]=dm;
            if(dm>bv){bv=dm; bi=i*1024+t;}
        }
#pragma unroll
        for(int i=8;i<16;i++){
            int n=i*1024+t;
            float dx=sx[n]-cx, dy=sy[n]-cy, dz=sz[n]-cz;
            float d=fmaf(dz,dz,fmaf(dx,dx,dy*dy));
            float dm=fminf(dmin[i],d); dmin[i]=dm;
            if(dm>bv){bv=dm; bi=n;}
        }
#pragma unroll
        for(int off=16; off>0; off>>=1){
            float ov=__shfl_down_sync(0xffffffffu,bv,off);
            int   oi=__shfl_down_sync(0xffffffffu,bi,off);
            if(ov>bv||(ov==bv&&oi<bi)){bv=ov; bi=oi;}
        }
        if(lane==0){redv[warp]=bv; redi[warp]=bi;}
        __syncthreads();
        if(warp==0){
            bv=redv[lane]; bi=redi[lane];
#pragma unroll
            for(int off=16; off>0; off>>=1){
                float ov=__shfl_down_sync(0xffffffffu,bv,off);
                int   oi=__shfl_down_sync(0xffffffffu,bi,off);
                if(ov>bv||(ov==bv&&oi<bi)){bv=ov; bi=oi;}
            }
            if(lane==0) s_win=bi;
        }
        __syncthreads();
        cur=s_win;
    }
}

__global__ void query_kernel(const float* __restrict__ xyz){
    int gw=(blockIdx.x*blockDim.x+threadIdx.x)>>5;
    int lane=threadIdx.x&31;
    if(gw>=B_*S_) return;
    int b=gw/S_;
    const float* nz=g_newxyz+(size_t)gw*3;
    float cx=nz[0],cy=nz[1],cz=nz[2];
    float srcn=fmaf(cz,cz,fmaf(cx,cx,cy*cy));
    const float* Xp=xyz+(size_t)b*3*N_;
    const float* pn=g_pnorm+(size_t)b*N_;
    int* dst=g_idx+(size_t)gw*K_;
    int count=0, first=0; bool haveFirst=false;
    for(int base=0; base<N_; base+=32){
        int n=base+lane;
        float dot=fmaf(cz,Xp[2*N_+n],fmaf(cy,Xp[N_+n],cx*Xp[n]));
        float d=fmaf(-2.0f,dot,srcn)+pn[n];
        bool ok=!(d>0.04f);
        unsigned m=__ballot_sync(0xffffffffu,ok);
        if(m){
            if(!haveFirst){first=base+__ffs(m)-1; haveFirst=true;}
            int rank=__popc(m&((1u<<lane)-1u));
            if(ok&&(count+rank)<K_) dst[count+rank]=n;
            count+=__popc(m);
            if(count>=K_) break;
        }
    }
    if(count<K_){
        for(int sl=count+lane; sl<K_; sl+=32) dst[sl]=first;
    }
}

// MODE: 0 = raw A load, 1 = bn+relu applied on A load, 2 = gather-build A (proj)
template<int K, int MODE>
__global__ void __launch_bounds__(256,2) gemm_kernel(const float* __restrict__ A,
                                                     const float* __restrict__ W,
                                                     float* __restrict__ Y,
                                                     const float* __restrict__ xyz){
    __shared__ float As[2][8][128];
    __shared__ float Bs[2][8][128];
    const int tid=threadIdx.x, m0=blockIdx.x<<7;
    const int tm=tid>>4, tn=tid&15;
    const int lrow=tid>>1, lcol=(tid&1)<<2;
    const int row=m0+lrow;

    const float* gsrc=nullptr; const float* xp=nullptr;
    float ncx=0.f,ncy=0.f,ncz=0.f; int jj=0;
    if(MODE==2){
        jj=g_idx[row];
        int bidx=row>>16;
        int cent=row>>5;
        ncx=g_newxyz[cent*3+0]; ncy=g_newxyz[cent*3+1]; ncz=g_newxyz[cent*3+2];
        gsrc=g_ptsT+((size_t)bidx*N_+jj)*C_;
        xp=xyz+(size_t)bidx*3*N_;
    }
    const float* Aptr=A+(size_t)row*K+lcol;
    const float* Wptr=W+(size_t)lrow*K+lcol;

    auto loadA=[&](int k0)->float4{
        if(MODE==2){
            float v[4];
#pragma unroll
            for(int q=0;q<4;q++){
                int c=k0+lcol+q;
                float t;
                if(c<3){ float nn=(c==0)?ncx:((c==1)?ncy:ncz); t=xp[(size_t)c*N_+jj]-nn; }
                else if(c<67) t=gsrc[c-3];
                else t=0.f;
                v[q]=t;
            }
            return make_float4(v[0],v[1],v[2],v[3]);
        }else{
            float4 a=*reinterpret_cast<const float4*>(Aptr+k0);
            if(MODE==1){
                int c=k0+lcol;
                float4 sc=*reinterpret_cast<const float4*>(&g_scale[c]);
                float4 sh=*reinterpret_cast<const float4*>(&g_shift[c]);
                a.x=fmaxf(0.f,fmaf(a.x,sc.x,sh.x));
                a.y=fmaxf(0.f,fmaf(a.y,sc.y,sh.y));
                a.z=fmaxf(0.f,fmaf(a.z,sc.z,sh.z));
                a.w=fmaxf(0.f,fmaf(a.w,sc.w,sh.w));
            }
            return a;
        }
    };

    float acc[8][8];
#pragma unroll
    for(int i=0;i<8;i++)
#pragma unroll
        for(int j=0;j<8;j++) acc[i][j]=0.0f;

    constexpr int NT=K/8;
    float4 av=loadA(0);
    float4 wv=*reinterpret_cast<const float4*>(Wptr);
    As[0][lcol+0][lrow]=av.x; As[0][lcol+1][lrow]=av.y; As[0][lcol+2][lrow]=av.z; As[0][lcol+3][lrow]=av.w;
    Bs[0][lcol+0][lrow]=wv.x; Bs[0][lcol+1][lrow]=wv.y; Bs[0][lcol+2][lrow]=wv.z; Bs[0][lcol+3][lrow]=wv.w;
    __syncthreads();

    for(int it=0; it<NT; ++it){
        const int cur=it&1;
        if(it+1<NT){
            av=loadA((it+1)*8);
            wv=*reinterpret_cast<const float4*>(Wptr+(it+1)*8);
        }
#pragma unroll
        for(int kk=0;kk<8;kk++){
            float4 a0=*reinterpret_cast<const float4*>(&As[cur][kk][tm<<3]);
            float4 a1=*reinterpret_cast<const float4*>(&As[cur][kk][(tm<<3)+4]);
            float4 b0=*reinterpret_cast<const float4*>(&Bs[cur][kk][tn<<3]);
            float4 b1=*reinterpret_cast<const float4*>(&Bs[cur][kk][(tn<<3)+4]);
            float a[8]={a0.x,a0.y,a0.z,a0.w,a1.x,a1.y,a1.z,a1.w};
            float w8[8]={b0.x,b0.y,b0.z,b0.w,b1.x,b1.y,b1.z,b1.w};
#pragma unroll
            for(int i=0;i<8;i++)
#pragma unroll
                for(int j=0;j<8;j++) acc[i][j]=fmaf(a[i],w8[j],acc[i][j]);
        }
        if(it+1<NT){
            const int nxt=cur^1;
            As[nxt][lcol+0][lrow]=av.x; As[nxt][lcol+1][lrow]=av.y; As[nxt][lcol+2][lrow]=av.z; As[nxt][lcol+3][lrow]=av.w;
            Bs[nxt][lcol+0][lrow]=wv.x; Bs[nxt][lcol+1][lrow]=wv.y; Bs[nxt][lcol+2][lrow]=wv.z; Bs[nxt][lcol+3][lrow]=wv.w;
        }
        __syncthreads();
    }

#pragma unroll
    for(int i=0;i<8;i++){
        float* yp=Y+(size_t)(m0+(tm<<3)+i)*CO_+(tn<<3);
        *reinterpret_cast<float4*>(yp)  =make_float4(acc[i][0],acc[i][1],acc[i][2],acc[i][3]);
        *reinterpret_cast<float4*>(yp+4)=make_float4(acc[i][4],acc[i][5],acc[i][6],acc[i][7]);
    }

    // fused BN-stats partials: per-column sum & sumsq over this block's 128 rows
    float cs[8], cq[8];
#pragma unroll
    for(int j=0;j<8;j++){
        float s=0.f,q=0.f;
#pragma unroll
        for(int i=0;i<8;i++){ float v=acc[i][j]; s+=v; q=fmaf(v,v,q); }
        cs[j]=s; cq[j]=q;
    }
    float* ss=&As[0][0][0];   // 2048 floats, free after final barrier
#pragma unroll
    for(int j=0;j<8;j++) ss[tm*128 + (tn<<3)+j]=cs[j];
    __syncthreads();
    if(tid<128){
        float s=0.f;
#pragma unroll
        for(int t=0;t<16;t++) s+=ss[t*128+tid];
        atomicAdd(&g_sum[tid], s);
    }
    __syncthreads();
#pragma unroll
    for(int j=0;j<8;j++) ss[tm*128 + (tn<<3)+j]=cq[j];
    __syncthreads();
    if(tid<128){
        float s=0.f;
#pragma unroll
        for(int t=0;t<16;t++) s+=ss[t*128+tid];
        atomicAdd(&g_sq[tid], s);
    }
}

__global__ void stats_zero(){
    int c=threadIdx.x;
    if(c<CO_){g_sum[c]=0.f; g_sq[c]=0.f;}
}

__global__ void finalize_kernel(const float* __restrict__ gg, const float* __restrict__ bb){
    int c=threadIdx.x;
    if(c<CO_){
        const float inv=1.0f/(float)M_;
        float mu=g_sum[c]*inv;
        float var=g_sq[c]*inv-mu*mu;
        float rs=rsqrtf(var+1e-5f);
        float sc=gg[c]*rs;
        g_scale[c]=sc;
        g_shift[c]=bb[c]-mu*sc;
    }
}

__global__ void bnrelu_kernel(const float4* __restrict__ Y, float4* __restrict__ X){
    size_t i=(size_t)blockIdx.x*blockDim.x+threadIdx.x;
    int c4=(int)(i&31)<<2;
    float4 y=Y[i],o;
    o.x=fmaxf(0.f,fmaf(y.x,g_scale[c4+0],g_shift[c4+0]));
    o.y=fmaxf(0.f,fmaf(y.y,g_scale[c4+1],g_shift[c4+1]));
    o.z=fmaxf(0.f,fmaf(y.z,g_scale[c4+2],g_shift[c4+2]));
    o.w=fmaxf(0.f,fmaf(y.w,g_scale[c4+3],g_shift[c4+3]));
    X[i]=o;
}

__global__ void bnresrelu_kernel(const float4* __restrict__ Y, float4* __restrict__ X){
    size_t i=(size_t)blockIdx.x*blockDim.x+threadIdx.x;
    int c4=(int)(i&31)<<2;
    float4 y=Y[i], x=X[i], o;
    o.x=fmaxf(0.f,fmaf(y.x,g_scale[c4+0],g_shift[c4+0])+x.x);
    o.y=fmaxf(0.f,fmaf(y.y,g_scale[c4+1],g_shift[c4+1])+x.y);
    o.z=fmaxf(0.f,fmaf(y.z,g_scale[c4+2],g_shift[c4+2])+x.z);
    o.w=fmaxf(0.f,fmaf(y.w,g_scale[c4+3],g_shift[c4+3])+x.w);
    X[i]=o;
}

// final bn + residual + relu fused into maxpool over K=32
__global__ void maxpool_fused(const float* __restrict__ Y2, const float* __restrict__ Xr,
                              float* __restrict__ out2){
    int id=blockIdx.x*blockDim.x+threadIdx.x;
    int c=id&127;
    int s=(id>>7)&(S_-1);
    int b=id>>18;
    size_t base=((size_t)(b*S_+s)*K_)*CO_+c;
    float sc=g_scale[c], sh=g_shift[c];
    float m=-1e30f;
#pragma unroll
    for(int k=0;k<K_;k++){
        float y=Y2[base+(size_t)k*CO_];
        float x=Xr[base+(size_t)k*CO_];
        float v=fmaxf(0.f, fmaf(y,sc,sh)+x);
        m=fmaxf(m,v);
    }
    out2[((size_t)b*CO_+c)*S_+s]=m;
}

extern "C" void kernel_launch(void* const* d_in, const int* in_sizes, int n_in,
                              void* d_out, int out_size){
    const float* xyz  =(const float*)d_in[0];
    const float* pts  =(const float*)d_in[1];
    const float* wproj=(const float*)d_in[2];
    const float* gproj=(const float*)d_in[3];
    const float* bproj=(const float*)d_in[4];
    const float* w1   =(const float*)d_in[5];
    const float* w2   =(const float*)d_in[6];
    const float* g1   =(const float*)d_in[7];
    const float* b1   =(const float*)d_in[8];
    const float* g2   =(const float*)d_in[9];
    const float* b2   =(const float*)d_in[10];
    float* out=(float*)d_out;

    void *pYv,*pXv,*pHv,*pWpv;
    cudaGetSymbolAddress(&pYv, g_Ybuf);
    cudaGetSymbolAddress(&pXv, g_Xbuf);
    cudaGetSymbolAddress(&pHv, g_Hbuf);
    cudaGetSymbolAddress(&pWpv,g_Wp);
    float* pY=(float*)pYv; float* pX=(float*)pXv;
    float* pH=(float*)pHv; float* pWp=(float*)pWpv;

    cudaFuncSetAttribute(fps_kernel, cudaFuncAttributeMaxDynamicSharedMemorySize, 3*N_*4);

    transpose_pts<<<dim3(N_/32, C_/32, B_), dim3(32,32)>>>(pts);
    pnorm_kernel<<<(B_*N_+1023)/1024,1024>>>(xyz);
    wpad_kernel<<<(CO_*KP0_+1023)/1024,1024>>>(wproj);

    fps_kernel<<<B_,1024,3*N_*4>>>(xyz,out);
    query_kernel<<<(B_*S_*32)/256,256>>>(xyz);

    const int EW_GRID=(M_*CO_/4)/1024;
    const int GG=M_/128;

    // projection: gather-fused GEMM (K=72) + fused stats
    stats_zero<<<1,128>>>();
    gemm_kernel<KP0_,2><<<GG,256>>>(pY, pWp, pY, xyz);
    finalize_kernel<<<1,128>>>(gproj,bproj);
    bnrelu_kernel<<<EW_GRID,1024>>>((const float4*)pY,(float4*)pX);

    for(int d=0; d<2; ++d){
        stats_zero<<<1,128>>>();
        gemm_kernel<128,0><<<GG,256>>>(pX, w1+(size_t)d*CO_*CO_, pY, xyz);
        finalize_kernel<<<1,128>>>(g1+d*CO_, b1+d*CO_);

        stats_zero<<<1,128>>>();
        gemm_kernel<128,1><<<GG,256>>>(pY, w2+(size_t)d*CO_*CO_, pH, xyz);
        finalize_kernel<<<1,128>>>(g2+d*CO_, b2+d*CO_);

        if(d==0)
            bnresrelu_kernel<<<EW_GRID,1024>>>((const float4*)pH,(float4*)pX);
    }

    maxpool_fused<<<(B_*S_*CO_)/256,256>>>(pH, pX, out + B_*3*S_);
}

// round 8
// speedup vs baseline: 1.1702x; 1.0819x over previous
#include <cuda_runtime.h>
#include <cstdint>

#define B_   4
#define N_   16384
#define C_   64
#define S_   2048
#define K_   32
#define M_   (B_*S_*K_)
#define CO_  128
#define KP0_ 72

__device__ __align__(16) float g_newxyz[B_*S_*3];
__device__ int   g_idx[B_*S_*K_];
__device__ __align__(16) float g_ptsT[(size_t)B_*N_*C_];
__device__ float g_pnorm[B_*N_];
__device__ __align__(16) float g_Ybuf[(size_t)M_*CO_];
__device__ __align__(16) float g_Xbuf[(size_t)M_*CO_];
__device__ __align__(16) float g_Hbuf[(size_t)M_*CO_];
__device__ __align__(16) float g_Wp[CO_*KP0_];
__device__ __align__(16) float g_sum[CO_];
__device__ __align__(16) float g_sq[CO_];
__device__ __align__(16) float g_scaleL[5*CO_];
__device__ __align__(16) float g_shiftL[5*CO_];

__global__ void transpose_pts(const float* __restrict__ pts){
    __shared__ float tile[32][33];
    int b=blockIdx.z, n0=blockIdx.x<<5, c0=blockIdx.y<<5;
    int tx=threadIdx.x, ty=threadIdx.y;
    tile[ty][tx]=pts[((size_t)b*C_+(c0+ty))*N_+n0+tx];
    __syncthreads();
    g_ptsT[((size_t)b*N_+(n0+ty))*C_+c0+tx]=tile[tx][ty];
}

__global__ void pnorm_kernel(const float* __restrict__ xyz){
    int id=blockIdx.x*blockDim.x+threadIdx.x;
    if(id>=B_*N_) return;
    int b=id/N_, n=id%N_;
    const float* Xp=xyz+(size_t)b*3*N_;
    float x=Xp[n], y=Xp[N_+n], z=Xp[2*N_+n];
    g_pnorm[id]=fmaf(z,z,fmaf(x,x,y*y));
}

__global__ void wpad_kernel(const float* __restrict__ w){
    int id=blockIdx.x*blockDim.x+threadIdx.x;
    if(id>=CO_*KP0_) return;
    int o=id/KP0_, k=id%KP0_;
    g_Wp[id]=(k<67)?w[o*67+k]:0.0f;
}

__global__ void __launch_bounds__(1024,1) fps_kernel(const float* __restrict__ xyz,
                                                     float* __restrict__ out0){
    extern __shared__ float fsm[];
    const int b=blockIdx.x, t=threadIdx.x;
    const float* Xp=xyz+(size_t)b*3*N_;
    float* sx=fsm; float* sy=fsm+N_; float* sz=fsm+2*N_;
    __shared__ int s_bmax;
    __shared__ int s_win;
    __shared__ float s_c[3];
    float px[8],py[8],pz[8],dmin[16];
#pragma unroll
    for(int i=0;i<8;i++){
        int n=i*1024+t;
        float x=Xp[n],y=Xp[N_+n],z=Xp[2*N_+n];
        sx[n]=x; sy[n]=y; sz[n]=z; px[i]=x; py[i]=y; pz[i]=z; dmin[i]=1e10f;
    }
#pragma unroll
    for(int i=8;i<16;i++){
        int n=i*1024+t;
        sx[n]=Xp[n]; sy[n]=Xp[N_+n]; sz[n]=Xp[2*N_+n]; dmin[i]=1e10f;
    }
    const int lane=t&31;
    if(t==0){
        // first centroid = point 0 (owned by this thread: chunk 0, t=0)
        s_c[0]=px[0]; s_c[1]=py[0]; s_c[2]=pz[0];
        out0[(size_t)b*3*S_+0]      =px[0];
        out0[(size_t)b*3*S_+S_+0]   =py[0];
        out0[(size_t)b*3*S_+2*S_+0] =pz[0];
        float* nz=g_newxyz+(size_t)b*S_*3;
        nz[0]=px[0]; nz[1]=py[0]; nz[2]=pz[0];
        s_bmax=0; s_win=0x7fffffff;
    }
    __syncthreads();

    for(int it=0; it<S_; ++it){
        const float cx=s_c[0],cy=s_c[1],cz=s_c[2];
        float bv=0.0f;
#pragma unroll
        for(int i=0;i<8;i++){
            float dx=px[i]-cx, dy=py[i]-cy, dz=pz[i]-cz;
            float d=fmaf(dz,dz,fmaf(dx,dx,dy*dy));
            float dm=fminf(dmin[i],d); dmin[i]=dm;
            bv=fmaxf(bv,dm);
        }
#pragma unroll
        for(int i=8;i<16;i++){
            int n=i*1024+t;
            float dx=sx[n]-cx, dy=sy[n]-cy, dz=sz[n]-cz;
            float d=fmaf(dz,dz,fmaf(dx,dx,dy*dy));
            float dm=fminf(dmin[i],d); dmin[i]=dm;
            bv=fmaxf(bv,dm);
        }
#pragma unroll
        for(int off=16; off>0; off>>=1)
            bv=fmaxf(bv,__shfl_xor_sync(0xffffffffu,bv,off));
        if(lane==0) atomicMax(&s_bmax, __float_as_int(bv));
        __syncthreads();
        const float bmax=__int_as_float(s_bmax);
        if(bv==bmax){                       // warp-uniform (bv = warp max on all lanes)
            int cand=0x7fffffff;
#pragma unroll
            for(int i=0;i<16;i++)
                if(dmin[i]==bmax) cand=min(cand, i*1024+t);
#pragma unroll
            for(int off=16; off>0; off>>=1)
                cand=min(cand,__shfl_xor_sync(0xffffffffu,cand,off));
            if(lane==0) atomicMin(&s_win,cand);
        }
        __syncthreads();
        if(t==0 && it+1<S_){
            int w=s_win;
            float cx2=sx[w], cy2=sy[w], cz2=sz[w];
            s_c[0]=cx2; s_c[1]=cy2; s_c[2]=cz2;
            out0[(size_t)b*3*S_+(it+1)]       =cx2;
            out0[(size_t)b*3*S_+S_+(it+1)]    =cy2;
            out0[(size_t)b*3*S_+2*S_+(it+1)]  =cz2;
            float* nz=g_newxyz+((size_t)b*S_+(it+1))*3;
            nz[0]=cx2; nz[1]=cy2; nz[2]=cz2;
            s_bmax=0; s_win=0x7fffffff;
        }
        __syncthreads();
    }
}

__global__ void query_kernel(const float* __restrict__ xyz){
    int gw=(blockIdx.x*blockDim.x+threadIdx.x)>>5;
    int lane=threadIdx.x&31;
    if(gw>=B_*S_) return;
    int b=gw/S_;
    const float* nz=g_newxyz+(size_t)gw*3;
    float cx=nz[0],cy=nz[1],cz=nz[2];
    float srcn=fmaf(cz,cz,fmaf(cx,cx,cy*cy));
    const float* Xp=xyz+(size_t)b*3*N_;
    const float* pn=g_pnorm+(size_t)b*N_;
    int* dst=g_idx+(size_t)gw*K_;
    int count=0, first=0; bool haveFirst=false;
    for(int base=0; base<N_; base+=32){
        int n=base+lane;
        float dot=fmaf(cz,Xp[2*N_+n],fmaf(cy,Xp[N_+n],cx*Xp[n]));
        float d=fmaf(-2.0f,dot,srcn)+pn[n];
        bool ok=!(d>0.04f);
        unsigned m=__ballot_sync(0xffffffffu,ok);
        if(m){
            if(!haveFirst){first=base+__ffs(m)-1; haveFirst=true;}
            int rank=__popc(m&((1u<<lane)-1u));
            if(ok&&(count+rank)<K_) dst[count+rank]=n;
            count+=__popc(m);
            if(count>=K_) break;
        }
    }
    if(count<K_){
        for(int sl=count+lane; sl<K_; sl+=32) dst[sl]=first;
    }
}

// MODE: 0 = raw A load, 1 = bn+relu applied on A load, 2 = gather-build A (proj)
template<int K, int MODE>
__global__ void __launch_bounds__(256,2) gemm_kernel(const float* __restrict__ A,
                                                     const float* __restrict__ W,
                                                     float* __restrict__ Y,
                                                     const float* __restrict__ xyz,
                                                     const float* __restrict__ scL,
                                                     const float* __restrict__ shL){
    __shared__ float As[2][8][128];
    __shared__ float Bs[2][8][128];
    const int tid=threadIdx.x, m0=blockIdx.x<<7;
    const int tm=tid>>4, tn=tid&15;
    const int lrow=tid>>1, lcol=(tid&1)<<2;
    const int row=m0+lrow;

    const float* gsrc=nullptr; const float* xp=nullptr;
    float ncx=0.f,ncy=0.f,ncz=0.f; int jj=0;
    if(MODE==2){
        jj=g_idx[row];
        int bidx=row>>16;
        int cent=row>>5;
        ncx=g_newxyz[cent*3+0]; ncy=g_newxyz[cent*3+1]; ncz=g_newxyz[cent*3+2];
        gsrc=g_ptsT+((size_t)bidx*N_+jj)*C_;
        xp=xyz+(size_t)bidx*3*N_;
    }
    const float* Aptr=A+(size_t)row*K+lcol;
    const float* Wptr=W+(size_t)lrow*K+lcol;

    auto loadA=[&](int k0)->float4{
        if(MODE==2){
            float v[4];
#pragma unroll
            for(int q=0;q<4;q++){
                int c=k0+lcol+q;
                float t;
                if(c<3){ float nn=(c==0)?ncx:((c==1)?ncy:ncz); t=xp[(size_t)c*N_+jj]-nn; }
                else if(c<67) t=gsrc[c-3];
                else t=0.f;
                v[q]=t;
            }
            return make_float4(v[0],v[1],v[2],v[3]);
        }else{
            float4 a=*reinterpret_cast<const float4*>(Aptr+k0);
            if(MODE==1){
                int c=k0+lcol;
                float4 sc=*reinterpret_cast<const float4*>(&scL[c]);
                float4 sh=*reinterpret_cast<const float4*>(&shL[c]);
                a.x=fmaxf(0.f,fmaf(a.x,sc.x,sh.x));
                a.y=fmaxf(0.f,fmaf(a.y,sc.y,sh.y));
                a.z=fmaxf(0.f,fmaf(a.z,sc.z,sh.z));
                a.w=fmaxf(0.f,fmaf(a.w,sc.w,sh.w));
            }
            return a;
        }
    };

    float acc[8][8];
#pragma unroll
    for(int i=0;i<8;i++)
#pragma unroll
        for(int j=0;j<8;j++) acc[i][j]=0.0f;

    constexpr int NT=K/8;
    float4 av=loadA(0);
    float4 wv=*reinterpret_cast<const float4*>(Wptr);
    As[0][lcol+0][lrow]=av.x; As[0][lcol+1][lrow]=av.y; As[0][lcol+2][lrow]=av.z; As[0][lcol+3][lrow]=av.w;
    Bs[0][lcol+0][lrow]=wv.x; Bs[0][lcol+1][lrow]=wv.y; Bs[0][lcol+2][lrow]=wv.z; Bs[0][lcol+3][lrow]=wv.w;
    __syncthreads();

    for(int it=0; it<NT; ++it){
        const int cur=it&1;
        if(it+1<NT){
            av=loadA((it+1)*8);
            wv=*reinterpret_cast<const float4*>(Wptr+(it+1)*8);
        }
#pragma unroll
        for(int kk=0;kk<8;kk++){
            float4 a0=*reinterpret_cast<const float4*>(&As[cur][kk][tm<<3]);
            float4 a1=*reinterpret_cast<const float4*>(&As[cur][kk][(tm<<3)+4]);
            float4 b0=*reinterpret_cast<const float4*>(&Bs[cur][kk][tn<<3]);
            float4 b1=*reinterpret_cast<const float4*>(&Bs[cur][kk][(tn<<3)+4]);
            float a[8]={a0.x,a0.y,a0.z,a0.w,a1.x,a1.y,a1.z,a1.w};
            float w8[8]={b0.x,b0.y,b0.z,b0.w,b1.x,b1.y,b1.z,b1.w};
#pragma unroll
            for(int i=0;i<8;i++)
#pragma unroll
                for(int j=0;j<8;j++) acc[i][j]=fmaf(a[i],w8[j],acc[i][j]);
        }
        if(it+1<NT){
            const int nxt=cur^1;
            As[nxt][lcol+0][lrow]=av.x; As[nxt][lcol+1][lrow]=av.y; As[nxt][lcol+2][lrow]=av.z; As[nxt][lcol+3][lrow]=av.w;
            Bs[nxt][lcol+0][lrow]=wv.x; Bs[nxt][lcol+1][lrow]=wv.y; Bs[nxt][lcol+2][lrow]=wv.z; Bs[nxt][lcol+3][lrow]=wv.w;
        }
        __syncthreads();
    }

#pragma unroll
    for(int i=0;i<8;i++){
        float* yp=Y+(size_t)(m0+(tm<<3)+i)*CO_+(tn<<3);
        *reinterpret_cast<float4*>(yp)  =make_float4(acc[i][0],acc[i][1],acc[i][2],acc[i][3]);
        *reinterpret_cast<float4*>(yp+4)=make_float4(acc[i][4],acc[i][5],acc[i][6],acc[i][7]);
    }

    float cs[8], cq[8];
#pragma unroll
    for(int j=0;j<8;j++){
        float s=0.f,q=0.f;
#pragma unroll
        for(int i=0;i<8;i++){ float v=acc[i][j]; s+=v; q=fmaf(v,v,q); }
        cs[j]=s; cq[j]=q;
    }
    float* ss=&As[0][0][0];
#pragma unroll
    for(int j=0;j<8;j++) ss[tm*128 + (tn<<3)+j]=cs[j];
    __syncthreads();
    if(tid<128){
        float s=0.f;
#pragma unroll
        for(int t=0;t<16;t++) s+=ss[t*128+tid];
        atomicAdd(&g_sum[tid], s);
    }
    __syncthreads();
#pragma unroll
    for(int j=0;j<8;j++) ss[tm*128 + (tn<<3)+j]=cq[j];
    __syncthreads();
    if(tid<128){
        float s=0.f;
#pragma unroll
        for(int t=0;t<16;t++) s+=ss[t*128+tid];
        atomicAdd(&g_sq[tid], s);
    }
}

__global__ void stats_zero(){
    int c=threadIdx.x;
    if(c<CO_){g_sum[c]=0.f; g_sq[c]=0.f;}
}

__global__ void finalize_kernel(const float* __restrict__ gg, const float* __restrict__ bb,
                                float* __restrict__ sc_out, float* __restrict__ sh_out){
    int c=threadIdx.x;
    if(c<CO_){
        const float inv=1.0f/(float)M_;
        float mu=g_sum[c]*inv;
        float var=g_sq[c]*inv-mu*mu;
        float rs=rsqrtf(var+1e-5f);
        float sc=gg[c]*rs;
        sc_out[c]=sc;
        sh_out[c]=bb[c]-mu*sc;
        g_sum[c]=0.f; g_sq[c]=0.f;   // ready for next layer
    }
}

// X_res = relu( bn2(y2) + relu(bn0(y0)) )
__global__ void bnres2_kernel(const float4* __restrict__ Y2, const float4* __restrict__ Y0,
                              float4* __restrict__ O,
                              const float* __restrict__ sc2, const float* __restrict__ sh2,
                              const float* __restrict__ sc0, const float* __restrict__ sh0){
    size_t i=(size_t)blockIdx.x*blockDim.x+threadIdx.x;
    int c4=(int)(i&31)<<2;
    float4 y2=Y2[i], y0=Y0[i], o;
    float x0=fmaxf(0.f,fmaf(y0.x,sc0[c4+0],sh0[c4+0]));
    float x1=fmaxf(0.f,fmaf(y0.y,sc0[c4+1],sh0[c4+1]));
    float x2=fmaxf(0.f,fmaf(y0.z,sc0[c4+2],sh0[c4+2]));
    float x3=fmaxf(0.f,fmaf(y0.w,sc0[c4+3],sh0[c4+3]));
    o.x=fmaxf(0.f,fmaf(y2.x,sc2[c4+0],sh2[c4+0])+x0);
    o.y=fmaxf(0.f,fmaf(y2.y,sc2[c4+1],sh2[c4+1])+x1);
    o.z=fmaxf(0.f,fmaf(y2.z,sc2[c4+2],sh2[c4+2])+x2);
    o.w=fmaxf(0.f,fmaf(y2.w,sc2[c4+3],sh2[c4+3])+x3);
    O[i]=o;
}

// out = max_k relu( bn4(y) + x_res )
__global__ void maxpool_fused(const float* __restrict__ Yb, const float* __restrict__ Xr,
                              float* __restrict__ out2,
                              const float* __restrict__ sc4, const float* __restrict__ sh4){
    int id=blockIdx.x*blockDim.x+threadIdx.x;
    int c=id&127;
    int s=(id>>7)&(S_-1);
    int b=id>>18;
    size_t base=((size_t)(b*S_+s)*K_)*CO_+c;
    float sc=sc4[c], sh=sh4[c];
    float m=-1e30f;
#pragma unroll
    for(int k=0;k<K_;k++){
        float y=Yb[base+(size_t)k*CO_];
        float x=Xr[base+(size_t)k*CO_];
        float v=fmaxf(0.f, fmaf(y,sc,sh)+x);
        m=fmaxf(m,v);
    }
    out2[((size_t)b*CO_+c)*S_+s]=m;
}

extern "C" void kernel_launch(void* const* d_in, const int* in_sizes, int n_in,
                              void* d_out, int out_size){
    const float* xyz  =(const float*)d_in[0];
    const float* pts  =(const float*)d_in[1];
    const float* wproj=(const float*)d_in[2];
    const float* gproj=(const float*)d_in[3];
    const float* bproj=(const float*)d_in[4];
    const float* w1   =(const float*)d_in[5];
    const float* w2   =(const float*)d_in[6];
    const float* g1   =(const float*)d_in[7];
    const float* b1   =(const float*)d_in[8];
    const float* g2   =(const float*)d_in[9];
    const float* b2   =(const float*)d_in[10];
    float* out=(float*)d_out;

    void *pYv,*pXv,*pHv,*pWpv,*pScv,*pShv;
    cudaGetSymbolAddress(&pYv, g_Ybuf);
    cudaGetSymbolAddress(&pXv, g_Xbuf);
    cudaGetSymbolAddress(&pHv, g_Hbuf);
    cudaGetSymbolAddress(&pWpv,g_Wp);
    cudaGetSymbolAddress(&pScv,g_scaleL);
    cudaGetSymbolAddress(&pShv,g_shiftL);
    float* pY=(float*)pYv; float* pX=(float*)pXv; float* pH=(float*)pHv;
    float* pWp=(float*)pWpv;
    float* scL=(float*)pScv; float* shL=(float*)pShv;

    cudaFuncSetAttribute(fps_kernel, cudaFuncAttributeMaxDynamicSharedMemorySize, 3*N_*4);

    transpose_pts<<<dim3(N_/32, C_/32, B_), dim3(32,32)>>>(pts);
    pnorm_kernel<<<(B_*N_+1023)/1024,1024>>>(xyz);
    wpad_kernel<<<(CO_*KP0_+1023)/1024,1024>>>(wproj);

    fps_kernel<<<B_,1024,3*N_*4>>>(xyz,out);
    query_kernel<<<(B_*S_*32)/256,256>>>(xyz);

    const int EW_GRID=(M_*CO_/4)/1024;
    const int GG=M_/128;

    stats_zero<<<1,128>>>();

    // layer 0: projection (gather-fused, K=72)
    gemm_kernel<KP0_,2><<<GG,256>>>(pY, pWp, pY, xyz, scL, shL);
    finalize_kernel<<<1,128>>>(gproj, bproj, scL+0*CO_, shL+0*CO_);

    // d=0
    gemm_kernel<128,1><<<GG,256>>>(pY, w1, pH, xyz, scL+0*CO_, shL+0*CO_);
    finalize_kernel<<<1,128>>>(g1, b1, scL+1*CO_, shL+1*CO_);
    gemm_kernel<128,1><<<GG,256>>>(pH, w2, pX, xyz, scL+1*CO_, shL+1*CO_);
    finalize_kernel<<<1,128>>>(g2, b2, scL+2*CO_, shL+2*CO_);
    bnres2_kernel<<<EW_GRID,1024>>>((const float4*)pX,(const float4*)pY,(float4*)pH,
                                    scL+2*CO_, shL+2*CO_, scL+0*CO_, shL+0*CO_);

    // d=1
    gemm_kernel<128,0><<<GG,256>>>(pH, w1+CO_*CO_, pY, xyz, scL, shL);
    finalize_kernel<<<1,128>>>(g1+CO_, b1+CO_, scL+3*CO_, shL+3*CO_);
    gemm_kernel<128,1><<<GG,256>>>(pY, w2+CO_*CO_, pX, xyz, scL+3*CO_, shL+3*CO_);
    finalize_kernel<<<1,128>>>(g2+CO_, b2+CO_, scL+4*CO_, shL+4*CO_);

    maxpool_fused<<<(B_*S_*CO_)/256,256>>>(pX, pH, out + B_*3*S_, scL+4*CO_, shL+4*CO_);
}

// round 9
// speedup vs baseline: 1.3024x; 1.1130x over previous
#include <cuda_runtime.h>
#include <cstdint>

#define B_   4
#define N_   16384
#define C_   64
#define S_   2048
#define K_   32
#define M_   (B_*S_*K_)
#define CO_  128
#define KP0_ 72

#define PACK_F32X2(out, lo, hi) \
    asm("mov.b64 %0, {%1, %2};" : "=l"(out) : "f"(lo), "f"(hi))
#define UNPACK_F32X2(lo, hi, in) \
    asm("mov.b64 {%0, %1}, %2;" : "=f"(lo), "=f"(hi) : "l"(in))
#define ADD_F32X2(out, a, b) \
    asm("add.rn.f32x2 %0, %1, %2;" : "=l"(out) : "l"(a), "l"(b))
#define MUL_F32X2(out, a, b) \
    asm("mul.rn.f32x2 %0, %1, %2;" : "=l"(out) : "l"(a), "l"(b))
#define FMA_F32X2(out, a, b, c) \
    asm("fma.rn.f32x2 %0, %1, %2, %3;" : "=l"(out) : "l"(a), "l"(b), "l"(c))

__device__ __align__(16) float g_newxyz[B_*S_*3];
__device__ int   g_idx[B_*S_*K_];
__device__ __align__(16) float g_ptsT[(size_t)B_*N_*C_];
__device__ float g_pnorm[B_*N_];
__device__ __align__(16) float g_Ybuf[(size_t)M_*CO_];
__device__ __align__(16) float g_Xbuf[(size_t)M_*CO_];
__device__ __align__(16) float g_Hbuf[(size_t)M_*CO_];
__device__ __align__(16) float g_Zbuf[(size_t)M_*CO_];
__device__ __align__(16) float g_Wp[CO_*KP0_];
__device__ __align__(16) float g_sum[CO_];
__device__ __align__(16) float g_sq[CO_];
__device__ __align__(16) float g_scaleL[5*CO_];
__device__ __align__(16) float g_shiftL[5*CO_];

__global__ void transpose_pts(const float* __restrict__ pts){
    __shared__ float tile[32][33];
    int b=blockIdx.z, n0=blockIdx.x<<5, c0=blockIdx.y<<5;
    int tx=threadIdx.x, ty=threadIdx.y;
    tile[ty][tx]=pts[((size_t)b*C_+(c0+ty))*N_+n0+tx];
    __syncthreads();
    g_ptsT[((size_t)b*N_+(n0+ty))*C_+c0+tx]=tile[tx][ty];
}

__global__ void pnorm_kernel(const float* __restrict__ xyz){
    int id=blockIdx.x*blockDim.x+threadIdx.x;
    if(id>=B_*N_) return;
    int b=id/N_, n=id%N_;
    const float* Xp=xyz+(size_t)b*3*N_;
    float x=Xp[n], y=Xp[N_+n], z=Xp[2*N_+n];
    g_pnorm[id]=fmaf(z,z,fmaf(x,x,y*y));
}

__global__ void wpad_kernel(const float* __restrict__ w){
    int id=blockIdx.x*blockDim.x+threadIdx.x;
    if(id>=CO_*KP0_) return;
    int o=id/KP0_, k=id%KP0_;
    g_Wp[id]=(k<67)?w[o*67+k]:0.0f;
}

// FPS: 512 threads/block, 1 block/batch. Points paired (n, n+8192), coords packed
// f32x2 in SMEM; pairs j=0..7 also register-resident. Distances computed with
// packed add/mul/fma (bitwise == scalar FADD/FMUL/FFMA chain of R8).
__global__ void __launch_bounds__(512,1) fps_kernel(const float* __restrict__ xyz,
                                                    float* __restrict__ out0){
    extern __shared__ unsigned long long fsmu[];
    const int b=blockIdx.x, t=threadIdx.x;
    const float* Xp=xyz+(size_t)b*3*N_;
    unsigned long long* sxu=fsmu;
    unsigned long long* syu=fsmu+8192;
    unsigned long long* szu=fsmu+16384;
    __shared__ int s_bmax[2];
    __shared__ int s_win[2];

    unsigned long long rx[8], ry[8], rz[8];
    float dmin[32];
#pragma unroll
    for(int j=0;j<16;j++){
        int n=j*512+t;
        float x0=Xp[n],        x1=Xp[n+8192];
        float y0=Xp[N_+n],     y1=Xp[N_+n+8192];
        float z0=Xp[2*N_+n],   z1=Xp[2*N_+n+8192];
        unsigned long long px,py,pz;
        PACK_F32X2(px,x0,x1); PACK_F32X2(py,y0,y1); PACK_F32X2(pz,z0,z1);
        sxu[n]=px; syu[n]=py; szu[n]=pz;
        if(j<8){ rx[j]=px; ry[j]=py; rz[j]=pz; }
        dmin[2*j]=1e10f; dmin[2*j+1]=1e10f;
    }
    float cx=Xp[0], cy=Xp[N_], cz=Xp[2*N_];
    if(t==0){
        out0[(size_t)b*3*S_+0]      =cx;
        out0[(size_t)b*3*S_+S_+0]   =cy;
        out0[(size_t)b*3*S_+2*S_+0] =cz;
        float* nz=g_newxyz+(size_t)b*S_*3;
        nz[0]=cx; nz[1]=cy; nz[2]=cz;
        s_bmax[0]=0; s_bmax[1]=0;
        s_win[0]=0x7fffffff; s_win[1]=0x7fffffff;
    }
    __syncthreads();

    const int lane=t&31;
    int p=0;
    for(int it=0; it<S_-1; ++it){
        float ncx=-cx, ncy=-cy, ncz=-cz;
        unsigned long long ncx2,ncy2,ncz2;
        PACK_F32X2(ncx2,ncx,ncx); PACK_F32X2(ncy2,ncy,ncy); PACK_F32X2(ncz2,ncz,ncz);
        float bv=0.0f;
#pragma unroll
        for(int j=0;j<8;j++){
            unsigned long long dx,dy,dz,tt,dd;
            ADD_F32X2(dx,rx[j],ncx2);
            ADD_F32X2(dy,ry[j],ncy2);
            ADD_F32X2(dz,rz[j],ncz2);
            MUL_F32X2(tt,dy,dy);
            FMA_F32X2(tt,dx,dx,tt);
            FMA_F32X2(dd,dz,dz,tt);
            float d0,d1; UNPACK_F32X2(d0,d1,dd);
            float m0=fminf(dmin[2*j],d0);   dmin[2*j]=m0;
            float m1=fminf(dmin[2*j+1],d1); dmin[2*j+1]=m1;
            bv=fmaxf(bv,m0); bv=fmaxf(bv,m1);
        }
#pragma unroll
        for(int j=8;j<16;j++){
            int n=j*512+t;
            unsigned long long dx,dy,dz,tt,dd;
            ADD_F32X2(dx,sxu[n],ncx2);
            ADD_F32X2(dy,syu[n],ncy2);
            ADD_F32X2(dz,szu[n],ncz2);
            MUL_F32X2(tt,dy,dy);
            FMA_F32X2(tt,dx,dx,tt);
            FMA_F32X2(dd,dz,dz,tt);
            float d0,d1; UNPACK_F32X2(d0,d1,dd);
            float m0=fminf(dmin[2*j],d0);   dmin[2*j]=m0;
            float m1=fminf(dmin[2*j+1],d1); dmin[2*j+1]=m1;
            bv=fmaxf(bv,m0); bv=fmaxf(bv,m1);
        }
#pragma unroll
        for(int off=16; off>0; off>>=1)
            bv=fmaxf(bv,__shfl_xor_sync(0xffffffffu,bv,off));
        if(lane==0) atomicMax(&s_bmax[p], __float_as_int(bv));
        __syncthreads();
        const float bmax=__int_as_float(s_bmax[p]);
        if(bv==bmax){                 // warp-uniform
            int cand=0x7fffffff;
#pragma unroll
            for(int k=0;k<32;k++){
                int idx=(k>>1)*512+t+((k&1)<<13);
                if(dmin[k]==bmax) cand=min(cand,idx);
            }
#pragma unroll
            for(int off=16; off>0; off>>=1)
                cand=min(cand,__shfl_xor_sync(0xffffffffu,cand,off));
            if(lane==0) atomicMin(&s_win[p],cand);
        }
        __syncthreads();
        const int w=s_win[p];
        // broadcast centroid fetch for next iteration
        int n=w&8191, hi=w>>13;
        float a0,a1;
        UNPACK_F32X2(a0,a1,sxu[n]); cx = hi? a1:a0;
        UNPACK_F32X2(a0,a1,syu[n]); cy = hi? a1:a0;
        UNPACK_F32X2(a0,a1,szu[n]); cz = hi? a1:a0;
        if(t==0){ s_bmax[p^1]=0; s_win[p^1]=0x7fffffff; }   // next-iter buffers
        if(t==32){                                           // off critical path
            out0[(size_t)b*3*S_+(it+1)]       =cx;
            out0[(size_t)b*3*S_+S_+(it+1)]    =cy;
            out0[(size_t)b*3*S_+2*S_+(it+1)]  =cz;
            float* nz=g_newxyz+((size_t)b*S_+(it+1))*3;
            nz[0]=cx; nz[1]=cy; nz[2]=cz;
        }
        p^=1;
    }
}

__global__ void query_kernel(const float* __restrict__ xyz){
    int gw=(blockIdx.x*blockDim.x+threadIdx.x)>>5;
    int lane=threadIdx.x&31;
    if(gw>=B_*S_) return;
    int b=gw/S_;
    const float* nz=g_newxyz+(size_t)gw*3;
    float cx=nz[0],cy=nz[1],cz=nz[2];
    float srcn=fmaf(cz,cz,fmaf(cx,cx,cy*cy));
    const float* Xp=xyz+(size_t)b*3*N_;
    const float* pn=g_pnorm+(size_t)b*N_;
    int* dst=g_idx+(size_t)gw*K_;
    int count=0, first=0; bool haveFirst=false;
    for(int base=0; base<N_; base+=32){
        int n=base+lane;
        float dot=fmaf(cz,Xp[2*N_+n],fmaf(cy,Xp[N_+n],cx*Xp[n]));
        float d=fmaf(-2.0f,dot,srcn)+pn[n];
        bool ok=!(d>0.04f);
        unsigned m=__ballot_sync(0xffffffffu,ok);
        if(m){
            if(!haveFirst){first=base+__ffs(m)-1; haveFirst=true;}
            int rank=__popc(m&((1u<<lane)-1u));
            if(ok&&(count+rank)<K_) dst[count+rank]=n;
            count+=__popc(m);
            if(count>=K_) break;
        }
    }
    if(count<K_){
        for(int sl=count+lane; sl<K_; sl+=32) dst[sl]=first;
    }
}

// MODE: 0=raw A, 1=bn+relu on A, 2=gather-build A (proj),
//       3=A = relu(bnA(a) + relu(bnB(a0)))  (residual-fused input)
template<int K, int MODE>
__global__ void __launch_bounds__(256,2) gemm_kernel(const float* __restrict__ A,
                                                     const float* __restrict__ W,
                                                     float* __restrict__ Y,
                                                     const float* __restrict__ xyz,
                                                     const float* __restrict__ scA,
                                                     const float* __restrict__ shA,
                                                     const float* __restrict__ A0,
                                                     const float* __restrict__ scB,
                                                     const float* __restrict__ shB){
    __shared__ float As[2][8][128];
    __shared__ float Bs[2][8][128];
    const int tid=threadIdx.x, m0=blockIdx.x<<7;
    const int tm=tid>>4, tn=tid&15;
    const int lrow=tid>>1, lcol=(tid&1)<<2;
    const int row=m0+lrow;

    const float* gsrc=nullptr; const float* xp=nullptr;
    float ncx=0.f,ncy=0.f,ncz=0.f; int jj=0;
    if(MODE==2){
        jj=g_idx[row];
        int bidx=row>>16;
        int cent=row>>5;
        ncx=g_newxyz[cent*3+0]; ncy=g_newxyz[cent*3+1]; ncz=g_newxyz[cent*3+2];
        gsrc=g_ptsT+((size_t)bidx*N_+jj)*C_;
        xp=xyz+(size_t)bidx*3*N_;
    }
    const float* Aptr=A+(size_t)row*K+lcol;
    const float* A0ptr=(MODE==3)? A0+(size_t)row*K+lcol : nullptr;
    const float* Wptr=W+(size_t)lrow*K+lcol;

    auto loadA=[&](int k0)->float4{
        if(MODE==2){
            float v[4];
#pragma unroll
            for(int q=0;q<4;q++){
                int c=k0+lcol+q;
                float t;
                if(c<3){ float nn=(c==0)?ncx:((c==1)?ncy:ncz); t=xp[(size_t)c*N_+jj]-nn; }
                else if(c<67) t=gsrc[c-3];
                else t=0.f;
                v[q]=t;
            }
            return make_float4(v[0],v[1],v[2],v[3]);
        }else{
            float4 a=*reinterpret_cast<const float4*>(Aptr+k0);
            if(MODE==1){
                int c=k0+lcol;
                float4 sc=*reinterpret_cast<const float4*>(&scA[c]);
                float4 sh=*reinterpret_cast<const float4*>(&shA[c]);
                a.x=fmaxf(0.f,fmaf(a.x,sc.x,sh.x));
                a.y=fmaxf(0.f,fmaf(a.y,sc.y,sh.y));
                a.z=fmaxf(0.f,fmaf(a.z,sc.z,sh.z));
                a.w=fmaxf(0.f,fmaf(a.w,sc.w,sh.w));
            }else if(MODE==3){
                int c=k0+lcol;
                float4 a0=*reinterpret_cast<const float4*>(A0ptr+k0);
                float4 sc=*reinterpret_cast<const float4*>(&scA[c]);
                float4 sh=*reinterpret_cast<const float4*>(&shA[c]);
                float4 s0=*reinterpret_cast<const float4*>(&scB[c]);
                float4 h0=*reinterpret_cast<const float4*>(&shB[c]);
                float x0=fmaxf(0.f,fmaf(a0.x,s0.x,h0.x));
                float x1=fmaxf(0.f,fmaf(a0.y,s0.y,h0.y));
                float x2=fmaxf(0.f,fmaf(a0.z,s0.z,h0.z));
                float x3=fmaxf(0.f,fmaf(a0.w,s0.w,h0.w));
                a.x=fmaxf(0.f,fmaf(a.x,sc.x,sh.x)+x0);
                a.y=fmaxf(0.f,fmaf(a.y,sc.y,sh.y)+x1);
                a.z=fmaxf(0.f,fmaf(a.z,sc.z,sh.z)+x2);
                a.w=fmaxf(0.f,fmaf(a.w,sc.w,sh.w)+x3);
            }
            return a;
        }
    };

    float acc[8][8];
#pragma unroll
    for(int i=0;i<8;i++)
#pragma unroll
        for(int j=0;j<8;j++) acc[i][j]=0.0f;

    constexpr int NT=K/8;
    float4 av=loadA(0);
    float4 wv=*reinterpret_cast<const float4*>(Wptr);
    As[0][lcol+0][lrow]=av.x; As[0][lcol+1][lrow]=av.y; As[0][lcol+2][lrow]=av.z; As[0][lcol+3][lrow]=av.w;
    Bs[0][lcol+0][lrow]=wv.x; Bs[0][lcol+1][lrow]=wv.y; Bs[0][lcol+2][lrow]=wv.z; Bs[0][lcol+3][lrow]=wv.w;
    __syncthreads();

    for(int it=0; it<NT; ++it){
        const int cur=it&1;
        if(it+1<NT){
            av=loadA((it+1)*8);
            wv=*reinterpret_cast<const float4*>(Wptr+(it+1)*8);
        }
#pragma unroll
        for(int kk=0;kk<8;kk++){
            float4 a0=*reinterpret_cast<const float4*>(&As[cur][kk][tm<<3]);
            float4 a1=*reinterpret_cast<const float4*>(&As[cur][kk][(tm<<3)+4]);
            float4 b0=*reinterpret_cast<const float4*>(&Bs[cur][kk][tn<<3]);
            float4 b1=*reinterpret_cast<const float4*>(&Bs[cur][kk][(tn<<3)+4]);
            float a[8]={a0.x,a0.y,a0.z,a0.w,a1.x,a1.y,a1.z,a1.w};
            float w8[8]={b0.x,b0.y,b0.z,b0.w,b1.x,b1.y,b1.z,b1.w};
#pragma unroll
            for(int i=0;i<8;i++)
#pragma unroll
                for(int j=0;j<8;j++) acc[i][j]=fmaf(a[i],w8[j],acc[i][j]);
        }
        if(it+1<NT){
            const int nxt=cur^1;
            As[nxt][lcol+0][lrow]=av.x; As[nxt][lcol+1][lrow]=av.y; As[nxt][lcol+2][lrow]=av.z; As[nxt][lcol+3][lrow]=av.w;
            Bs[nxt][lcol+0][lrow]=wv.x; Bs[nxt][lcol+1][lrow]=wv.y; Bs[nxt][lcol+2][lrow]=wv.z; Bs[nxt][lcol+3][lrow]=wv.w;
        }
        __syncthreads();
    }

#pragma unroll
    for(int i=0;i<8;i++){
        float* yp=Y+(size_t)(m0+(tm<<3)+i)*CO_+(tn<<3);
        *reinterpret_cast<float4*>(yp)  =make_float4(acc[i][0],acc[i][1],acc[i][2],acc[i][3]);
        *reinterpret_cast<float4*>(yp+4)=make_float4(acc[i][4],acc[i][5],acc[i][6],acc[i][7]);
    }

    float cs[8], cq[8];
#pragma unroll
    for(int j=0;j<8;j++){
        float s=0.f,q=0.f;
#pragma unroll
        for(int i=0;i<8;i++){ float v=acc[i][j]; s+=v; q=fmaf(v,v,q); }
        cs[j]=s; cq[j]=q;
    }
    float* ss=&As[0][0][0];
#pragma unroll
    for(int j=0;j<8;j++) ss[tm*128 + (tn<<3)+j]=cs[j];
    __syncthreads();
    if(tid<128){
        float s=0.f;
#pragma unroll
        for(int t=0;t<16;t++) s+=ss[t*128+tid];
        atomicAdd(&g_sum[tid], s);
    }
    __syncthreads();
#pragma unroll
    for(int j=0;j<8;j++) ss[tm*128 + (tn<<3)+j]=cq[j];
    __syncthreads();
    if(tid<128){
        float s=0.f;
#pragma unroll
        for(int t=0;t<16;t++) s+=ss[t*128+tid];
        atomicAdd(&g_sq[tid], s);
    }
}

__global__ void stats_zero(){
    int c=threadIdx.x;
    if(c<CO_){g_sum[c]=0.f; g_sq[c]=0.f;}
}

__global__ void finalize_kernel(const float* __restrict__ gg, const float* __restrict__ bb,
                                float* __restrict__ sc_out, float* __restrict__ sh_out){
    int c=threadIdx.x;
    if(c<CO_){
        const float inv=1.0f/(float)M_;
        float mu=g_sum[c]*inv;
        float var=g_sq[c]*inv-mu*mu;
        float rs=rsqrtf(var+1e-5f);
        float sc=gg[c]*rs;
        sc_out[c]=sc;
        sh_out[c]=bb[c]-mu*sc;
        g_sum[c]=0.f; g_sq[c]=0.f;
    }
}

// out = max_k relu( bn4(y4) + relu( bn2(y2) + relu(bn0(y0)) ) )
__global__ void maxpool3_kernel(const float* __restrict__ Y4, const float* __restrict__ Y2,
                                const float* __restrict__ Y0, float* __restrict__ out2,
                                const float* __restrict__ scL, const float* __restrict__ shL){
    int id=blockIdx.x*blockDim.x+threadIdx.x;
    int c=id&127;
    int s=(id>>7)&(S_-1);
    int b=id>>18;
    size_t base=((size_t)(b*S_+s)*K_)*CO_+c;
    float sc0=scL[0*CO_+c], sh0=shL[0*CO_+c];
    float sc2=scL[2*CO_+c], sh2=shL[2*CO_+c];
    float sc4=scL[4*CO_+c], sh4=shL[4*CO_+c];
    float m=-1e30f;
#pragma unroll
    for(int k=0;k<K_;k++){
        size_t o=base+(size_t)k*CO_;
        float x0=fmaxf(0.f,fmaf(Y0[o],sc0,sh0));
        float xr=fmaxf(0.f,fmaf(Y2[o],sc2,sh2)+x0);
        float v =fmaxf(0.f,fmaf(Y4[o],sc4,sh4)+xr);
        m=fmaxf(m,v);
    }
    out2[((size_t)b*CO_+c)*S_+s]=m;
}

extern "C" void kernel_launch(void* const* d_in, const int* in_sizes, int n_in,
                              void* d_out, int out_size){
    const float* xyz  =(const float*)d_in[0];
    const float* pts  =(const float*)d_in[1];
    const float* wproj=(const float*)d_in[2];
    const float* gproj=(const float*)d_in[3];
    const float* bproj=(const float*)d_in[4];
    const float* w1   =(const float*)d_in[5];
    const float* w2   =(const float*)d_in[6];
    const float* g1   =(const float*)d_in[7];
    const float* b1   =(const float*)d_in[8];
    const float* g2   =(const float*)d_in[9];
    const float* b2   =(const float*)d_in[10];
    float* out=(float*)d_out;

    void *pYv,*pXv,*pHv,*pZv,*pWpv,*pScv,*pShv;
    cudaGetSymbolAddress(&pYv, g_Ybuf);
    cudaGetSymbolAddress(&pXv, g_Xbuf);
    cudaGetSymbolAddress(&pHv, g_Hbuf);
    cudaGetSymbolAddress(&pZv, g_Zbuf);
    cudaGetSymbolAddress(&pWpv,g_Wp);
    cudaGetSymbolAddress(&pScv,g_scaleL);
    cudaGetSymbolAddress(&pShv,g_shiftL);
    float* pY=(float*)pYv; float* pX=(float*)pXv; float* pH=(float*)pHv;
    float* pZ=(float*)pZv; float* pWp=(float*)pWpv;
    float* scL=(float*)pScv; float* shL=(float*)pShv;

    cudaFuncSetAttribute(fps_kernel, cudaFuncAttributeMaxDynamicSharedMemorySize, 3*8192*8);

    transpose_pts<<<dim3(N_/32, C_/32, B_), dim3(32,32)>>>(pts);
    pnorm_kernel<<<(B_*N_+1023)/1024,1024>>>(xyz);
    wpad_kernel<<<(CO_*KP0_+1023)/1024,1024>>>(wproj);

    fps_kernel<<<B_,512,3*8192*8>>>(xyz,out);
    query_kernel<<<(B_*S_*32)/256,256>>>(xyz);

    const int GG=M_/128;
    stats_zero<<<1,128>>>();

    // layer 0: projection (gather-fused, K=72) -> y0 (pY)
    gemm_kernel<KP0_,2><<<GG,256>>>(pY, pWp, pY, xyz, scL, shL, nullptr, nullptr, nullptr);
    finalize_kernel<<<1,128>>>(gproj, bproj, scL+0*CO_, shL+0*CO_);

    // d=0: w1 on bn0(y0) -> y1 (pH); w2 on bn1(y1) -> y2 (pX)
    gemm_kernel<128,1><<<GG,256>>>(pY, w1, pH, xyz, scL+0*CO_, shL+0*CO_, nullptr, nullptr, nullptr);
    finalize_kernel<<<1,128>>>(g1, b1, scL+1*CO_, shL+1*CO_);
    gemm_kernel<128,1><<<GG,256>>>(pH, w2, pX, xyz, scL+1*CO_, shL+1*CO_, nullptr, nullptr, nullptr);
    finalize_kernel<<<1,128>>>(g2, b2, scL+2*CO_, shL+2*CO_);

    // d=1: w1 on relu(bn2(y2)+relu(bn0(y0))) -> y3 (pZ); w2 on bn3(y3) -> y4 (pH)
    gemm_kernel<128,3><<<GG,256>>>(pX, w1+CO_*CO_, pZ, xyz,
                                   scL+2*CO_, shL+2*CO_, pY, scL+0*CO_, shL+0*CO_);
    finalize_kernel<<<1,128>>>(g1+CO_, b1+CO_, scL+3*CO_, shL+3*CO_);
    gemm_kernel<128,1><<<GG,256>>>(pZ, w2+CO_*CO_, pH, xyz, scL+3*CO_, shL+3*CO_, nullptr, nullptr, nullptr);
    finalize_kernel<<<1,128>>>(g2+CO_, b2+CO_, scL+4*CO_, shL+4*CO_);

    maxpool3_kernel<<<(B_*S_*CO_)/256,256>>>(pH, pX, pY, out + B_*3*S_, scL, shL);
}